// round 1
// baseline (speedup 1.0000x reference)
#include <cuda_runtime.h>
#include <math.h>
#include <stddef.h>

#define BATCH 4
#define CIN 64
#define COUT 64
#define LSEQ 131072
#define KW 9
#define PADW 4
#define TILE 128
#define XW (TILE + 2 * PADW) /* 136 */
#define NTHREADS 256
#define NTILES (BATCH * (LSEQ / TILE)) /* 4096 */

#define SMEM_FLOATS (KW * CIN * COUT + CIN * XW + 3 * XW + KW * TILE)

__device__ double g_sum[COUT];
__device__ double g_sumsq[COUT];
__device__ float g_scale[COUT];
__device__ float g_shift[COUT];

__device__ __forceinline__ float2 ffma2(float2 a, float2 b, float2 c) {
    float2 d;
    asm("fma.rn.f32x2 %0, %1, %2, %3;"
        : "=l"(reinterpret_cast<unsigned long long &>(d))
        : "l"(reinterpret_cast<unsigned long long &>(a)),
          "l"(reinterpret_cast<unsigned long long &>(b)),
          "l"(reinterpret_cast<unsigned long long &>(c)));
    return d;
}

__device__ __forceinline__ float2 fmul2(float2 a, float2 b) {
    float2 d;
    asm("mul.rn.f32x2 %0, %1, %2;"
        : "=l"(reinterpret_cast<unsigned long long &>(d))
        : "l"(reinterpret_cast<unsigned long long &>(a)),
          "l"(reinterpret_cast<unsigned long long &>(b)));
    return d;
}

__global__ void zero_stats_kernel() {
    int i = threadIdx.x;
    if (i < COUT) {
        g_sum[i] = 0.0;
        g_sumsq[i] = 0.0;
    }
}

__global__ __launch_bounds__(NTHREADS, 1) void conv_kernel(
    const float* __restrict__ x, const float* __restrict__ coords,
    const float* __restrict__ W, const float* __restrict__ bias,
    float* __restrict__ out) {
    extern __shared__ float smem[];
    float* Wsh = smem;                    // [KW][CIN][COUT]  (Wsh[k][c][o] = W[o][c][k])
    float* xsh = Wsh + KW * CIN * COUT;   // [CIN][XW]
    float* csh = xsh + CIN * XW;          // [3][XW]
    float* wsh = csh + 3 * XW;            // [KW][TILE]

    const int tid = threadIdx.x;
    const int tx = tid & 31;  // L lane: cols tx, tx+32, tx+64, tx+96
    const int ty = tid >> 5;  // Cout group: rows ty*8 .. ty*8+7

    // One-time: stage W transposed into smem (coalesced global reads).
    for (int i = tid; i < KW * CIN * COUT; i += NTHREADS) {
        int o = i / (CIN * KW);
        int rem = i - o * (CIN * KW);
        int c = rem / KW;
        int k = rem - c * KW;
        Wsh[(k * CIN + c) * COUT + o] = W[i];
    }

    for (int t = blockIdx.x; t < NTILES; t += gridDim.x) {
        const int b = t / (LSEQ / TILE);
        const int l0 = (t - b * (LSEQ / TILE)) * TILE;
        __syncthreads();  // previous tile's consumers done before overwriting stage buffers

        const float* xb = x + (size_t)b * CIN * LSEQ;
        for (int i = tid; i < CIN * XW; i += NTHREADS) {
            int c = i / XW;
            int j = i - c * XW;
            int l = l0 - PADW + j;
            xsh[i] = (l >= 0 && l < LSEQ) ? xb[(size_t)c * LSEQ + l] : 0.0f;
        }
        const float* cb = coords + (size_t)b * 3 * LSEQ;
        for (int i = tid; i < 3 * XW; i += NTHREADS) {
            int d = i / XW;
            int j = i - d * XW;
            int l = l0 - PADW + j;
            csh[i] = (l >= 0 && l < LSEQ) ? cb[(size_t)d * LSEQ + l] : 0.0f;
        }
        __syncthreads();

        // Gaussian spatial weights: w[k][lc] = exp(-0.5 * |c[lc+k-4] - c[lc]|^2)
        for (int i = tid; i < KW * TILE; i += NTHREADS) {
            int k = i / TILE;
            int lc = i - k * TILE;
            float d0 = csh[lc + k] - csh[lc + PADW];
            float d1 = csh[XW + lc + k] - csh[XW + lc + PADW];
            float d2 = csh[2 * XW + lc + k] - csh[2 * XW + lc + PADW];
            float dist2 = d0 * d0 + d1 * d1 + d2 * d2;
            wsh[i] = __expf(-0.5f * dist2);
        }
        __syncthreads();

        float2 acc[8][2];
#pragma unroll
        for (int r = 0; r < 8; r++) {
            acc[r][0] = make_float2(0.f, 0.f);
            acc[r][1] = make_float2(0.f, 0.f);
        }

#pragma unroll
        for (int k = 0; k < KW; k++) {
            const float2 wv0 = make_float2(wsh[k * TILE + tx], wsh[k * TILE + 32 + tx]);
            const float2 wv1 = make_float2(wsh[k * TILE + 64 + tx], wsh[k * TILE + 96 + tx]);
            const float* xrow = xsh + tx + k;
            const float* wrow = Wsh + k * CIN * COUT + ty * 8;
#pragma unroll 4
            for (int c = 0; c < CIN; c++) {
                float b0 = xrow[c * XW];
                float b1 = xrow[c * XW + 32];
                float b2 = xrow[c * XW + 64];
                float b3 = xrow[c * XW + 96];
                float2 bw0 = fmul2(make_float2(b0, b1), wv0);
                float2 bw1 = fmul2(make_float2(b2, b3), wv1);
                float4 a0 = *reinterpret_cast<const float4*>(wrow + c * COUT);
                float4 a1 = *reinterpret_cast<const float4*>(wrow + c * COUT + 4);
                acc[0][0] = ffma2(make_float2(a0.x, a0.x), bw0, acc[0][0]);
                acc[0][1] = ffma2(make_float2(a0.x, a0.x), bw1, acc[0][1]);
                acc[1][0] = ffma2(make_float2(a0.y, a0.y), bw0, acc[1][0]);
                acc[1][1] = ffma2(make_float2(a0.y, a0.y), bw1, acc[1][1]);
                acc[2][0] = ffma2(make_float2(a0.z, a0.z), bw0, acc[2][0]);
                acc[2][1] = ffma2(make_float2(a0.z, a0.z), bw1, acc[2][1]);
                acc[3][0] = ffma2(make_float2(a0.w, a0.w), bw0, acc[3][0]);
                acc[3][1] = ffma2(make_float2(a0.w, a0.w), bw1, acc[3][1]);
                acc[4][0] = ffma2(make_float2(a1.x, a1.x), bw0, acc[4][0]);
                acc[4][1] = ffma2(make_float2(a1.x, a1.x), bw1, acc[4][1]);
                acc[5][0] = ffma2(make_float2(a1.y, a1.y), bw0, acc[5][0]);
                acc[5][1] = ffma2(make_float2(a1.y, a1.y), bw1, acc[5][1]);
                acc[6][0] = ffma2(make_float2(a1.z, a1.z), bw0, acc[6][0]);
                acc[6][1] = ffma2(make_float2(a1.z, a1.z), bw1, acc[6][1]);
                acc[7][0] = ffma2(make_float2(a1.w, a1.w), bw0, acc[7][0]);
                acc[7][1] = ffma2(make_float2(a1.w, a1.w), bw1, acc[7][1]);
            }
        }

        // Epilogue: +bias, store raw, accumulate per-channel batch stats.
        float* outb = out + (size_t)b * COUT * LSEQ;
#pragma unroll
        for (int r = 0; r < 8; r++) {
            int o = ty * 8 + r;
            float bz = __ldg(&bias[o]);
            float v0 = acc[r][0].x + bz;
            float v1 = acc[r][0].y + bz;
            float v2 = acc[r][1].x + bz;
            float v3 = acc[r][1].y + bz;
            size_t base = (size_t)o * LSEQ + l0 + tx;
            outb[base] = v0;
            outb[base + 32] = v1;
            outb[base + 64] = v2;
            outb[base + 96] = v3;
            float s1 = (v0 + v1) + (v2 + v3);
            float s2 = (v0 * v0 + v1 * v1) + (v2 * v2 + v3 * v3);
#pragma unroll
            for (int off = 16; off > 0; off >>= 1) {
                s1 += __shfl_xor_sync(0xffffffffu, s1, off);
                s2 += __shfl_xor_sync(0xffffffffu, s2, off);
            }
            if (tx == 0) {
                atomicAdd(&g_sum[o], (double)s1);
                atomicAdd(&g_sumsq[o], (double)s2);
            }
        }
    }
}

__global__ void stats_kernel(const float* __restrict__ gamma,
                             const float* __restrict__ beta) {
    int o = threadIdx.x;
    if (o < COUT) {
        double N = (double)BATCH * (double)LSEQ;
        double mean = g_sum[o] / N;
        double var = g_sumsq[o] / N - mean * mean;
        double rstd = 1.0 / sqrt(var + 1e-5);
        float sc = gamma[o] * (float)rstd;
        g_scale[o] = sc;
        g_shift[o] = beta[o] - (float)mean * sc;
    }
}

__global__ void norm_kernel(float* __restrict__ out) {
    const size_t total4 = (size_t)BATCH * COUT * LSEQ / 4;
    size_t stride = (size_t)gridDim.x * blockDim.x;
    for (size_t i = (size_t)blockIdx.x * blockDim.x + threadIdx.x; i < total4;
         i += stride) {
        float4 v = reinterpret_cast<float4*>(out)[i];
        int ch = (int)((i * 4 / LSEQ)) & (COUT - 1);
        float sc = g_scale[ch];
        float sh = g_shift[ch];
        v.x = fmaxf(fmaf(v.x, sc, sh), 0.0f);
        v.y = fmaxf(fmaf(v.y, sc, sh), 0.0f);
        v.z = fmaxf(fmaf(v.z, sc, sh), 0.0f);
        v.w = fmaxf(fmaf(v.w, sc, sh), 0.0f);
        reinterpret_cast<float4*>(out)[i] = v;
    }
}

extern "C" void kernel_launch(void* const* d_in, const int* in_sizes, int n_in,
                              void* d_out, int out_size) {
    const float* x = (const float*)d_in[0];       // [4,64,131072]
    const float* coords = (const float*)d_in[1];  // [4,3,131072]
    const float* W = (const float*)d_in[2];       // [64,64,9]
    const float* bias = (const float*)d_in[3];    // [64]
    const float* gamma = (const float*)d_in[4];   // [64]
    const float* beta = (const float*)d_in[5];    // [64]
    float* out = (float*)d_out;

    const size_t smem = SMEM_FLOATS * sizeof(float);
    cudaFuncSetAttribute(conv_kernel, cudaFuncAttributeMaxDynamicSharedMemorySize,
                         (int)smem);
    int sms = 148;
    cudaDeviceGetAttribute(&sms, cudaDevAttrMultiProcessorCount, 0);

    zero_stats_kernel<<<1, 128>>>();
    conv_kernel<<<sms, NTHREADS, smem>>>(x, coords, W, bias, out);
    stats_kernel<<<1, 64>>>(gamma, beta);
    norm_kernel<<<8192, 256>>>(out);
}